// round 16
// baseline (speedup 1.0000x reference)
#include <cuda_runtime.h>
#include <cuda_fp16.h>
#include <stdint.h>

#define S_LEN 4096
#define DM    768
#define NH    12
#define HD    64
#define KW    (DM / 2)

// Q prescale: 0.125 (1/sqrt(64)) * log2(e) -> scores in log2 domain
#define QSCALE 0.18033688011112042f
#define ONESH2 0x3C003C00u   // fp16x2 {1.0, 1.0}

__device__ __align__(16) __half   hQ[S_LEN * DM], hK[S_LEN * DM], hV[S_LEN * DM];
__device__ __align__(16) uint32_t pWq[KW * DM], pWk[KW * DM], pWv[KW * DM], pWo[KW * DM];
__device__ __align__(16) __half   g_q16[S_LEN * DM];
__device__ __align__(16) __half   g_k16[S_LEN * DM];
__device__ __align__(16) __half   g_vT [DM * S_LEN];   // [h*64+dv][key]
__device__ __align__(16) __half   g_a16[S_LEN * DM];

__device__ __forceinline__ uint32_t f2h2(float lo, float hi) {
    uint32_t r;
    asm("cvt.rn.f16x2.f32 %0, %1, %2;" : "=r"(r) : "f"(hi), "f"(lo));
    return r;
}
__device__ __forceinline__ uint32_t hsub2u(uint32_t a, uint32_t b) {
    uint32_t r;
    asm("sub.rn.f16x2 %0, %1, %2;" : "=r"(r) : "r"(a), "r"(b));
    return r;
}
__device__ __forceinline__ uint32_t ex2h2(uint32_t x) {
    uint32_t r;
    asm("ex2.approx.f16x2 %0, %1;" : "=r"(r) : "r"(x));
    return r;
}
__device__ __forceinline__ void mma_f16(float c[4],
    uint32_t a0, uint32_t a1, uint32_t a2, uint32_t a3,
    uint32_t b0, uint32_t b1)
{
    asm volatile(
        "mma.sync.aligned.m16n8k16.row.col.f32.f16.f16.f32 "
        "{%0,%1,%2,%3}, {%4,%5,%6,%7}, {%8,%9}, {%0,%1,%2,%3};"
        : "+f"(c[0]), "+f"(c[1]), "+f"(c[2]), "+f"(c[3])
        : "r"(a0), "r"(a1), "r"(a2), "r"(a3), "r"(b0), "r"(b1));
}
__device__ __forceinline__ void ldsm4(uint32_t& r0, uint32_t& r1,
                                      uint32_t& r2, uint32_t& r3, uint32_t addr)
{
    asm volatile("ldmatrix.sync.aligned.m8n8.x4.shared.b16 {%0,%1,%2,%3}, [%4];"
        : "=r"(r0), "=r"(r1), "=r"(r2), "=r"(r3) : "r"(addr));
}
__device__ __forceinline__ void cp16(uint32_t dst_smem, const void* src) {
    asm volatile("cp.async.cg.shared.global [%0], [%1], 16;"
                 :: "r"(dst_smem), "l"(src));
}
#define CP_COMMIT()   asm volatile("cp.async.commit_group;" ::: "memory")
#define CP_WAIT_ALL() asm volatile("cp.async.wait_all;" ::: "memory")

// ---------------------------------------------------------------------------
// Prologue: fused fp32->fp16 convert (y<3) + weight pack (y>=3)
// ---------------------------------------------------------------------------
__global__ __launch_bounds__(256) void prep(
    const float* __restrict__ Q, const float* __restrict__ K,
    const float* __restrict__ V,
    const float* __restrict__ Wq, const float* __restrict__ Wk,
    const float* __restrict__ Wv, const float* __restrict__ Wo)
{
    int y = blockIdx.y;
    int i = blockIdx.x * 256 + threadIdx.x;
    if (y < 3) {
        const float* src = (y == 0) ? Q : (y == 1) ? K : V;
        __half* dst = (y == 0) ? hQ : (y == 1) ? hK : hV;
        float4 a = ((const float4*)src)[2 * i];
        float4 b = ((const float4*)src)[2 * i + 1];
        ((uint4*)dst)[i] = make_uint4(f2h2(a.x, a.y), f2h2(a.z, a.w),
                                      f2h2(b.x, b.y), f2h2(b.z, b.w));
    } else {
        if (i >= KW * DM) return;
        const float* W = (y == 3) ? Wq : (y == 4) ? Wk : (y == 5) ? Wv : Wo;
        uint32_t* P = (y == 3) ? pWq : (y == 4) ? pWk : (y == 5) ? pWv : pWo;
        int kp = i / DM, n = i - kp * DM;
        P[i] = f2h2(W[(size_t)(2 * kp) * DM + n],
                    W[(size_t)(2 * kp + 1) * DM + n]);
    }
}

// ---------------------------------------------------------------------------
// GEMM fp16 (unchanged, passing)
// ---------------------------------------------------------------------------
#define GA_ST 20
#define GB_ST 72
#define GBUF  (256 * GA_ST + 16 * GB_ST)
#define GEMM_SMEM (2 * GBUF * 4)

__device__ __forceinline__ void gemm16_body(
    const __half* __restrict__ A, const uint32_t* __restrict__ Bp,
    const float* __restrict__ bias, void* __restrict__ Cout,
    int bx, int by, int mode, float oscale)
{
    extern __shared__ uint32_t sm[];
    const uint32_t sb = (uint32_t)__cvta_generic_to_shared(sm);

    const int tid  = threadIdx.x;
    const int warp = tid >> 5, lane = tid & 31;
    const int g = lane >> 2, tg = lane & 3;
    const int m0 = by * 256, n0 = bx * 64;
    const int wbase = warp * 64;

    float acc[4][8][4];
#pragma unroll
    for (int mt = 0; mt < 4; mt++)
#pragma unroll
        for (int nt = 0; nt < 8; nt++)
#pragma unroll
            for (int c = 0; c < 4; c++) acc[mt][nt][c] = 0.f;

    auto issue = [&](int t, int b) {
        uint32_t base = sb + (uint32_t)(b * GBUF) * 4;
#pragma unroll
        for (int it = 0; it < 8; it++) {
            int idx = it * 128 + tid;
            int r = idx >> 2, c16 = idx & 3;
            cp16(base + (uint32_t)(r * GA_ST + c16 * 4) * 4,
                 &A[(size_t)(m0 + r) * DM + t * 32 + c16 * 8]);
        }
#pragma unroll
        for (int it = 0; it < 2; it++) {
            int idx = it * 128 + tid;
            int kp = idx >> 4, nc = idx & 15;
            cp16(base + (uint32_t)(256 * GA_ST + kp * GB_ST + nc * 4) * 4,
                 &Bp[(size_t)(t * 16 + kp) * DM + n0 + nc * 4]);
        }
        CP_COMMIT();
    };

    issue(0, 0);

    const int NT = DM / 32;
    for (int t = 0; t < NT; t++) {
        CP_WAIT_ALL();
        __syncthreads();
        if (t + 1 < NT) issue(t + 1, (t + 1) & 1);

        const uint32_t* Ab = sm + (t & 1) * GBUF;
        const uint32_t* Bb = Ab + 256 * GA_ST;

#pragma unroll
        for (int c = 0; c < 2; c++) {
            int kcw = c * 8 + tg;
            uint32_t a[4][4];
#pragma unroll
            for (int mt = 0; mt < 4; mt++) {
                int r = wbase + mt * 16 + g;
                a[mt][0] = Ab[r * GA_ST + kcw];
                a[mt][1] = Ab[(r + 8) * GA_ST + kcw];
                a[mt][2] = Ab[r * GA_ST + kcw + 4];
                a[mt][3] = Ab[(r + 8) * GA_ST + kcw + 4];
            }
#pragma unroll
            for (int nt = 0; nt < 8; nt++) {
                int cn = nt * 8 + g;
                uint32_t b0 = Bb[kcw * GB_ST + cn];
                uint32_t b1 = Bb[(kcw + 4) * GB_ST + cn];
#pragma unroll
                for (int mt = 0; mt < 4; mt++)
                    mma_f16(acc[mt][nt], a[mt][0], a[mt][1], a[mt][2], a[mt][3],
                            b0, b1);
            }
        }
        __syncthreads();
    }

    if (mode == 0) {
        uint32_t* out = (uint32_t*)Cout;
#pragma unroll
        for (int mt = 0; mt < 4; mt++)
#pragma unroll
            for (int nt = 0; nt < 8; nt++) {
                int r = m0 + wbase + mt * 16 + g;
                int c = n0 + nt * 8 + 2 * tg;
                out[((size_t)r * DM + c) >> 1] =
                    f2h2(acc[mt][nt][0] * oscale, acc[mt][nt][1] * oscale);
                out[((size_t)(r + 8) * DM + c) >> 1] =
                    f2h2(acc[mt][nt][2] * oscale, acc[mt][nt][3] * oscale);
            }
    } else if (mode == 1) {
        __half* out = (__half*)Cout;
#pragma unroll
        for (int mt = 0; mt < 4; mt++)
#pragma unroll
            for (int nt = 0; nt < 8; nt++) {
                int r = m0 + wbase + mt * 16 + g;
                int c = n0 + nt * 8 + 2 * tg;
                out[(size_t)c * S_LEN + r]           = __float2half_rn(acc[mt][nt][0]);
                out[(size_t)(c + 1) * S_LEN + r]     = __float2half_rn(acc[mt][nt][1]);
                out[(size_t)c * S_LEN + r + 8]       = __float2half_rn(acc[mt][nt][2]);
                out[(size_t)(c + 1) * S_LEN + r + 8] = __float2half_rn(acc[mt][nt][3]);
            }
    } else {
        float* out = (float*)Cout;
#pragma unroll
        for (int mt = 0; mt < 4; mt++)
#pragma unroll
            for (int nt = 0; nt < 8; nt++) {
                int r = m0 + wbase + mt * 16 + g;
                int c = n0 + nt * 8 + 2 * tg;
                float b0 = bias[c], b1 = bias[c + 1];
                *(float2*)&out[(size_t)r * DM + c] =
                    make_float2(acc[mt][nt][0] + b0, acc[mt][nt][1] + b1);
                *(float2*)&out[(size_t)(r + 8) * DM + c] =
                    make_float2(acc[mt][nt][2] + b0, acc[mt][nt][3] + b1);
            }
    }
}

__global__ __launch_bounds__(128) void proj3(float* dummy) {
    if (blockIdx.z == 0)
        gemm16_body(hQ, pWq, nullptr, g_q16, blockIdx.x, blockIdx.y, 0, QSCALE);
    else if (blockIdx.z == 1)
        gemm16_body(hK, pWk, nullptr, g_k16, blockIdx.x, blockIdx.y, 0, 1.f);
    else
        gemm16_body(hV, pWv, nullptr, g_vT, blockIdx.x, blockIdx.y, 1, 1.f);
}

__global__ __launch_bounds__(128) void outg(const float* bias, float* out) {
    gemm16_body(g_a16, pWo, bias, out, blockIdx.x, blockIdx.y, 2, 1.f);
}

// ---------------------------------------------------------------------------
// Flash attention fp16, software-pipelined: 64 q-rows x 1 head, 128 thr,
// 3 blocks/SM, 3 SMEM tile-buffers. Steady state: softmax(kt) then joint
// mma phase PV(kt) + S(kt+1). ldmatrix B-frags; log2 softmax; ones-mma sums.
// ---------------------------------------------------------------------------
#define KT_ST 36
#define TBUF  (2 * 64 * KT_ST)          // K+V words per tile = 4608
#define ATTN_SMEM (3 * TBUF * 4)        // 55296 B

__global__ __launch_bounds__(128, 3) void attn16(float* dummy)
{
    extern __shared__ uint32_t smd[];
    const uint32_t sb = (uint32_t)__cvta_generic_to_shared(smd);

    const int h = blockIdx.y;
    const int t = blockIdx.x;
    const int iq = (t & 1) ? (63 - (t >> 1)) : (t >> 1);
    const int tid = threadIdx.x, warp = tid >> 5, lane = tid & 31;
    const int g = lane >> 2, tg = lane & 3;
    const int hoff = h * HD;
    const int qrow0 = iq * 64 + warp * 16 + g;

    const uint32_t lm_ofs =
        (uint32_t)(((lane >> 4) * 8 + (lane & 7)) * KT_ST + ((lane >> 3) & 1) * 4) * 4;

    // Q fragments (pre-scaled by QSCALE)
    const uint32_t* qw = (const uint32_t*)g_q16;
    uint32_t qf[4][4];
    {
        size_t b0 = ((size_t)qrow0 * DM + hoff) >> 1;
        size_t b1 = ((size_t)(qrow0 + 8) * DM + hoff) >> 1;
#pragma unroll
        for (int c = 0; c < 4; c++) {
            qf[c][0] = qw[b0 + c * 8 + tg];
            qf[c][1] = qw[b1 + c * 8 + tg];
            qf[c][2] = qw[b0 + c * 8 + tg + 4];
            qf[c][3] = qw[b1 + c * 8 + tg + 4];
        }
    }

    float of[8][4];
#pragma unroll
    for (int nt = 0; nt < 8; nt++)
#pragma unroll
        for (int c = 0; c < 4; c++) of[nt][c] = 0.f;
    float m0r = -1e30f, m1r = -1e30f, l0 = 0.f, l1 = 0.f;

    auto issue = [&](int kt, int b) {
        uint32_t base = sb + (uint32_t)(b * TBUF) * 4;
#pragma unroll
        for (int it = 0; it < 4; it++) {
            int idx = it * 128 + tid;
            int r = idx >> 3, c16 = idx & 7;
            cp16(base + (uint32_t)(r * KT_ST + c16 * 4) * 4,
                 &g_k16[(size_t)(kt * 64 + r) * DM + hoff + c16 * 8]);
            cp16(base + (uint32_t)(64 * KT_ST + r * KT_ST + c16 * 4) * 4,
                 &g_vT[(size_t)(hoff + r) * S_LEN + kt * 64 + c16 * 8]);
        }
        CP_COMMIT();
    };

    const int ktmax = iq;

    // prologue: tile 0 loaded, S(0) computed, tile 1 in flight
    issue(0, 0);
    CP_WAIT_ALL();
    __syncthreads();
    if (ktmax >= 1) issue(1, 1);

    float s[8][4];
#pragma unroll
    for (int nt = 0; nt < 8; nt++)
#pragma unroll
        for (int c = 0; c < 4; c++) s[nt][c] = 0.f;
    {
        uint32_t Kb = sb + lm_ofs;   // buf 0
#pragma unroll
        for (int c = 0; c < 4; c++)
#pragma unroll
            for (int ntp = 0; ntp < 4; ntp++) {
                uint32_t b0a, b1a, b0b, b1b;
                ldsm4(b0a, b1a, b0b, b1b,
                      Kb + (uint32_t)(ntp * 16 * KT_ST + c * 8) * 4);
                mma_f16(s[2 * ntp],     qf[c][0], qf[c][1], qf[c][2], qf[c][3], b0a, b1a);
                mma_f16(s[2 * ntp + 1], qf[c][0], qf[c][1], qf[c][2], qf[c][3], b0b, b1b);
            }
    }

    for (int kt = 0; kt <= ktmax; kt++) {
        // causal mask only on the diagonal tile
        if (kt == iq) {
#pragma unroll
            for (int nt = 0; nt < 8; nt++) {
                int col = kt * 64 + nt * 8 + 2 * tg;
                if (col     > qrow0)     s[nt][0] = -1e30f;
                if (col + 1 > qrow0)     s[nt][1] = -1e30f;
                if (col     > qrow0 + 8) s[nt][2] = -1e30f;
                if (col + 1 > qrow0 + 8) s[nt][3] = -1e30f;
            }
        }

        // softmax(kt): max + rescale + exp -> ah
        float rm0 = -1e30f, rm1 = -1e30f;
#pragma unroll
        for (int nt = 0; nt < 8; nt++) {
            rm0 = fmaxf(rm0, fmaxf(s[nt][0], s[nt][1]));
            rm1 = fmaxf(rm1, fmaxf(s[nt][2], s[nt][3]));
        }
#pragma unroll
        for (int off = 1; off <= 2; off <<= 1) {
            rm0 = fmaxf(rm0, __shfl_xor_sync(0xFFFFFFFFu, rm0, off));
            rm1 = fmaxf(rm1, __shfl_xor_sync(0xFFFFFFFFu, rm1, off));
        }
        float nm0 = fmaxf(m0r, rm0), nm1 = fmaxf(m1r, rm1);
        float al0 = exp2f(m0r - nm0), al1 = exp2f(m1r - nm1);
        m0r = nm0;  m1r = nm1;
        l0 *= al0;  l1 *= al1;
#pragma unroll
        for (int nt = 0; nt < 8; nt++) {
            of[nt][0] *= al0; of[nt][1] *= al0;
            of[nt][2] *= al1; of[nt][3] *= al1;
        }
        uint32_t ah[4][4];
        uint32_t nm0p = f2h2(nm0, nm0), nm1p = f2h2(nm1, nm1);
#pragma unroll
        for (int c = 0; c < 4; c++) {
            ah[c][0] = ex2h2(hsub2u(f2h2(s[2*c][0],   s[2*c][1]),   nm0p));
            ah[c][1] = ex2h2(hsub2u(f2h2(s[2*c][2],   s[2*c][3]),   nm1p));
            ah[c][2] = ex2h2(hsub2u(f2h2(s[2*c+1][0], s[2*c+1][1]), nm0p));
            ah[c][3] = ex2h2(hsub2u(f2h2(s[2*c+1][2], s[2*c+1][3]), nm1p));
        }

        float sacc[4] = {0.f, 0.f, 0.f, 0.f};
        uint32_t Vb = sb + (uint32_t)((kt % 3) * TBUF + 64 * KT_ST) * 4 + lm_ofs;

        if (kt < ktmax) {
            // wait tile kt+1; start load of tile kt+2 into buf (kt+2)%3
            CP_WAIT_ALL();
            __syncthreads();
            if (kt + 1 < ktmax) issue(kt + 2, (kt + 2) % 3);

            uint32_t Kb = sb + (uint32_t)(((kt + 1) % 3) * TBUF) * 4 + lm_ofs;

            // joint phase: PV(kt) + S(kt+1), interleaved independent mmas
#pragma unroll
            for (int nt = 0; nt < 8; nt++)
#pragma unroll
                for (int c = 0; c < 4; c++) s[nt][c] = 0.f;

#pragma unroll
            for (int c = 0; c < 4; c++) {
#pragma unroll
                for (int ntp = 0; ntp < 4; ntp++) {
                    uint32_t v0, v1, v2, v3, k0, k1, k2, k3;
                    ldsm4(v0, v1, v2, v3,
                          Vb + (uint32_t)(ntp * 16 * KT_ST + c * 8) * 4);
                    ldsm4(k0, k1, k2, k3,
                          Kb + (uint32_t)(ntp * 16 * KT_ST + c * 8) * 4);
                    mma_f16(of[2 * ntp],     ah[c][0], ah[c][1], ah[c][2], ah[c][3], v0, v1);
                    mma_f16(s[2 * ntp],      qf[c][0], qf[c][1], qf[c][2], qf[c][3], k0, k1);
                    mma_f16(of[2 * ntp + 1], ah[c][0], ah[c][1], ah[c][2], ah[c][3], v2, v3);
                    mma_f16(s[2 * ntp + 1],  qf[c][0], qf[c][1], qf[c][2], qf[c][3], k2, k3);
                }
                mma_f16(sacc, ah[c][0], ah[c][1], ah[c][2], ah[c][3], ONESH2, ONESH2);
            }
        } else {
            // last tile: PV only
#pragma unroll
            for (int c = 0; c < 4; c++) {
#pragma unroll
                for (int ntp = 0; ntp < 4; ntp++) {
                    uint32_t v0, v1, v2, v3;
                    ldsm4(v0, v1, v2, v3,
                          Vb + (uint32_t)(ntp * 16 * KT_ST + c * 8) * 4);
                    mma_f16(of[2 * ntp],     ah[c][0], ah[c][1], ah[c][2], ah[c][3], v0, v1);
                    mma_f16(of[2 * ntp + 1], ah[c][0], ah[c][1], ah[c][2], ah[c][3], v2, v3);
                }
                mma_f16(sacc, ah[c][0], ah[c][1], ah[c][2], ah[c][3], ONESH2, ONESH2);
            }
        }
        l0 += sacc[0];
        l1 += sacc[2];
    }

    // epilogue -> fp16 att buffer
    uint32_t* out = (uint32_t*)g_a16;
    float inv0 = 1.f / l0, inv1 = 1.f / l1;
#pragma unroll
    for (int nt = 0; nt < 8; nt++) {
        int c = hoff + nt * 8 + 2 * tg;
        out[((size_t)qrow0 * DM + c) >> 1] =
            f2h2(of[nt][0] * inv0, of[nt][1] * inv0);
        out[((size_t)(qrow0 + 8) * DM + c) >> 1] =
            f2h2(of[nt][2] * inv1, of[nt][3] * inv1);
    }
}

// ---------------------------------------------------------------------------
// Launch
// ---------------------------------------------------------------------------
extern "C" void kernel_launch(void* const* d_in, const int* in_sizes, int n_in,
                              void* d_out, int out_size)
{
    const float* Q  = (const float*)d_in[0];
    const float* K  = (const float*)d_in[1];
    const float* V  = (const float*)d_in[2];
    const float* Wq = (const float*)d_in[3];
    const float* Wk = (const float*)d_in[4];
    const float* Wv = (const float*)d_in[5];
    const float* Wo = (const float*)d_in[6];
    const float* bo = (const float*)d_in[7];
    float* out = (float*)d_out;

    static bool attr_set = false;
    if (!attr_set) {
        cudaFuncSetAttribute(proj3, cudaFuncAttributeMaxDynamicSharedMemorySize,
                             GEMM_SMEM);
        cudaFuncSetAttribute(outg, cudaFuncAttributeMaxDynamicSharedMemorySize,
                             GEMM_SMEM);
        cudaFuncSetAttribute(attn16, cudaFuncAttributeMaxDynamicSharedMemorySize,
                             ATTN_SMEM);
        attr_set = true;
    }

    prep<<<dim3(S_LEN * DM / 8 / 256, 7), 256>>>(Q, K, V, Wq, Wk, Wv, Wo);

    proj3<<<dim3(DM / 64, S_LEN / 256, 3), 128, GEMM_SMEM>>>(nullptr);

    attn16<<<dim3(S_LEN / 64, NH), 128, ATTN_SMEM>>>(nullptr);

    outg<<<dim3(DM / 64, S_LEN / 256), 128, GEMM_SMEM>>>(bo, out);
}

// round 17
// speedup vs baseline: 1.0722x; 1.0722x over previous
#include <cuda_runtime.h>
#include <cuda_fp16.h>
#include <stdint.h>

#define S_LEN 4096
#define DM    768
#define NH    12
#define HD    64
#define KW    (DM / 2)

// Q prescale: 0.125 (1/sqrt(64)) * log2(e) -> scores in log2 domain
#define QSCALE 0.18033688011112042f
#define ONESH2 0x3C003C00u   // fp16x2 {1.0, 1.0}

__device__ __align__(16) __half   hQ[S_LEN * DM], hK[S_LEN * DM], hV[S_LEN * DM];
__device__ __align__(16) uint32_t pWq[KW * DM], pWk[KW * DM], pWv[KW * DM], pWo[KW * DM];
__device__ __align__(16) __half   g_q16[S_LEN * DM];
__device__ __align__(16) __half   g_k16[S_LEN * DM];
__device__ __align__(16) __half   g_vT [DM * S_LEN];   // [h*64+dv][key]
__device__ __align__(16) __half   g_a16[S_LEN * DM];

__device__ __forceinline__ uint32_t f2h2(float lo, float hi) {
    uint32_t r;
    asm("cvt.rn.f16x2.f32 %0, %1, %2;" : "=r"(r) : "f"(hi), "f"(lo));
    return r;
}
__device__ __forceinline__ uint32_t hsub2u(uint32_t a, uint32_t b) {
    uint32_t r;
    asm("sub.rn.f16x2 %0, %1, %2;" : "=r"(r) : "r"(a), "r"(b));
    return r;
}
__device__ __forceinline__ uint32_t ex2h2(uint32_t x) {
    uint32_t r;
    asm("ex2.approx.f16x2 %0, %1;" : "=r"(r) : "r"(x));
    return r;
}
__device__ __forceinline__ void mma_f16(float c[4],
    uint32_t a0, uint32_t a1, uint32_t a2, uint32_t a3,
    uint32_t b0, uint32_t b1)
{
    asm volatile(
        "mma.sync.aligned.m16n8k16.row.col.f32.f16.f16.f32 "
        "{%0,%1,%2,%3}, {%4,%5,%6,%7}, {%8,%9}, {%0,%1,%2,%3};"
        : "+f"(c[0]), "+f"(c[1]), "+f"(c[2]), "+f"(c[3])
        : "r"(a0), "r"(a1), "r"(a2), "r"(a3), "r"(b0), "r"(b1));
}
__device__ __forceinline__ void ldsm4(uint32_t& r0, uint32_t& r1,
                                      uint32_t& r2, uint32_t& r3, uint32_t addr)
{
    asm volatile("ldmatrix.sync.aligned.m8n8.x4.shared.b16 {%0,%1,%2,%3}, [%4];"
        : "=r"(r0), "=r"(r1), "=r"(r2), "=r"(r3) : "r"(addr));
}
__device__ __forceinline__ void cp16(uint32_t dst_smem, const void* src) {
    asm volatile("cp.async.cg.shared.global [%0], [%1], 16;"
                 :: "r"(dst_smem), "l"(src));
}
#define CP_COMMIT()   asm volatile("cp.async.commit_group;" ::: "memory")
#define CP_WAIT_ALL() asm volatile("cp.async.wait_all;" ::: "memory")

// ---------------------------------------------------------------------------
// Prologue: fused fp32->fp16 convert (y<3) + weight pack (y>=3)
// ---------------------------------------------------------------------------
__global__ __launch_bounds__(256) void prep(
    const float* __restrict__ Q, const float* __restrict__ K,
    const float* __restrict__ V,
    const float* __restrict__ Wq, const float* __restrict__ Wk,
    const float* __restrict__ Wv, const float* __restrict__ Wo)
{
    int y = blockIdx.y;
    int i = blockIdx.x * 256 + threadIdx.x;
    if (y < 3) {
        const float* src = (y == 0) ? Q : (y == 1) ? K : V;
        __half* dst = (y == 0) ? hQ : (y == 1) ? hK : hV;
        float4 a = ((const float4*)src)[2 * i];
        float4 b = ((const float4*)src)[2 * i + 1];
        ((uint4*)dst)[i] = make_uint4(f2h2(a.x, a.y), f2h2(a.z, a.w),
                                      f2h2(b.x, b.y), f2h2(b.z, b.w));
    } else {
        if (i >= KW * DM) return;
        const float* W = (y == 3) ? Wq : (y == 4) ? Wk : (y == 5) ? Wv : Wo;
        uint32_t* P = (y == 3) ? pWq : (y == 4) ? pWk : (y == 5) ? pWv : pWo;
        int kp = i / DM, n = i - kp * DM;
        P[i] = f2h2(W[(size_t)(2 * kp) * DM + n],
                    W[(size_t)(2 * kp + 1) * DM + n]);
    }
}

// ---------------------------------------------------------------------------
// Projection GEMM fp16, mt=4: 256x64 tiles (576 blocks, good occupancy).
// ---------------------------------------------------------------------------
#define GA_ST 20
#define GB_ST 72
#define GBUF  (256 * GA_ST + 16 * GB_ST)
#define GEMM_SMEM (2 * GBUF * 4)

__device__ __forceinline__ void gemm16_body(
    const __half* __restrict__ A, const uint32_t* __restrict__ Bp,
    void* __restrict__ Cout, int bx, int by, int mode, float oscale)
{
    extern __shared__ uint32_t sm[];
    const uint32_t sb = (uint32_t)__cvta_generic_to_shared(sm);

    const int tid  = threadIdx.x;
    const int warp = tid >> 5, lane = tid & 31;
    const int g = lane >> 2, tg = lane & 3;
    const int m0 = by * 256, n0 = bx * 64;
    const int wbase = warp * 64;

    float acc[4][8][4];
#pragma unroll
    for (int mt = 0; mt < 4; mt++)
#pragma unroll
        for (int nt = 0; nt < 8; nt++)
#pragma unroll
            for (int c = 0; c < 4; c++) acc[mt][nt][c] = 0.f;

    auto issue = [&](int t, int b) {
        uint32_t base = sb + (uint32_t)(b * GBUF) * 4;
#pragma unroll
        for (int it = 0; it < 8; it++) {
            int idx = it * 128 + tid;
            int r = idx >> 2, c16 = idx & 3;
            cp16(base + (uint32_t)(r * GA_ST + c16 * 4) * 4,
                 &A[(size_t)(m0 + r) * DM + t * 32 + c16 * 8]);
        }
#pragma unroll
        for (int it = 0; it < 2; it++) {
            int idx = it * 128 + tid;
            int kp = idx >> 4, nc = idx & 15;
            cp16(base + (uint32_t)(256 * GA_ST + kp * GB_ST + nc * 4) * 4,
                 &Bp[(size_t)(t * 16 + kp) * DM + n0 + nc * 4]);
        }
        CP_COMMIT();
    };

    issue(0, 0);

    const int NT = DM / 32;
    for (int t = 0; t < NT; t++) {
        CP_WAIT_ALL();
        __syncthreads();
        if (t + 1 < NT) issue(t + 1, (t + 1) & 1);

        const uint32_t* Ab = sm + (t & 1) * GBUF;
        const uint32_t* Bb = Ab + 256 * GA_ST;

#pragma unroll
        for (int c = 0; c < 2; c++) {
            int kcw = c * 8 + tg;
            uint32_t a[4][4];
#pragma unroll
            for (int mt = 0; mt < 4; mt++) {
                int r = wbase + mt * 16 + g;
                a[mt][0] = Ab[r * GA_ST + kcw];
                a[mt][1] = Ab[(r + 8) * GA_ST + kcw];
                a[mt][2] = Ab[r * GA_ST + kcw + 4];
                a[mt][3] = Ab[(r + 8) * GA_ST + kcw + 4];
            }
#pragma unroll
            for (int nt = 0; nt < 8; nt++) {
                int cn = nt * 8 + g;
                uint32_t b0 = Bb[kcw * GB_ST + cn];
                uint32_t b1 = Bb[(kcw + 4) * GB_ST + cn];
#pragma unroll
                for (int mt = 0; mt < 4; mt++)
                    mma_f16(acc[mt][nt], a[mt][0], a[mt][1], a[mt][2], a[mt][3],
                            b0, b1);
            }
        }
        __syncthreads();
    }

    if (mode == 0) {
        uint32_t* out = (uint32_t*)Cout;
#pragma unroll
        for (int mt = 0; mt < 4; mt++)
#pragma unroll
            for (int nt = 0; nt < 8; nt++) {
                int r = m0 + wbase + mt * 16 + g;
                int c = n0 + nt * 8 + 2 * tg;
                out[((size_t)r * DM + c) >> 1] =
                    f2h2(acc[mt][nt][0] * oscale, acc[mt][nt][1] * oscale);
                out[((size_t)(r + 8) * DM + c) >> 1] =
                    f2h2(acc[mt][nt][2] * oscale, acc[mt][nt][3] * oscale);
            }
    } else {
        __half* out = (__half*)Cout;
#pragma unroll
        for (int mt = 0; mt < 4; mt++)
#pragma unroll
            for (int nt = 0; nt < 8; nt++) {
                int r = m0 + wbase + mt * 16 + g;
                int c = n0 + nt * 8 + 2 * tg;
                out[(size_t)c * S_LEN + r]           = __float2half_rn(acc[mt][nt][0]);
                out[(size_t)(c + 1) * S_LEN + r]     = __float2half_rn(acc[mt][nt][1]);
                out[(size_t)c * S_LEN + r + 8]       = __float2half_rn(acc[mt][nt][2]);
                out[(size_t)(c + 1) * S_LEN + r + 8] = __float2half_rn(acc[mt][nt][3]);
            }
    }
}

__global__ __launch_bounds__(128) void proj3(float* dummy) {
    if (blockIdx.z == 0)
        gemm16_body(hQ, pWq, g_q16, blockIdx.x, blockIdx.y, 0, QSCALE);
    else if (blockIdx.z == 1)
        gemm16_body(hK, pWk, g_k16, blockIdx.x, blockIdx.y, 0, 1.f);
    else
        gemm16_body(hV, pWv, g_vT, blockIdx.x, blockIdx.y, 1, 1.f);
}

// ---------------------------------------------------------------------------
// Output GEMM fp16, mt=2: 128x64 tiles -> 384 blocks (concurrency over
// bytes-efficiency; outg was occupancy-starved at 192 blocks).
// ---------------------------------------------------------------------------
#define G2BUF (128 * GA_ST + 16 * GB_ST)        // 3712 words
#define GEMM2_SMEM (2 * G2BUF * 4)              // 29696 B

__global__ __launch_bounds__(128) void outg(const float* __restrict__ bias,
                                            float* __restrict__ Cout)
{
    extern __shared__ uint32_t sm[];
    const uint32_t sb = (uint32_t)__cvta_generic_to_shared(sm);
    const __half* A = g_a16;
    const uint32_t* Bp = pWo;

    const int tid  = threadIdx.x;
    const int warp = tid >> 5, lane = tid & 31;
    const int g = lane >> 2, tg = lane & 3;
    const int m0 = blockIdx.y * 128, n0 = blockIdx.x * 64;
    const int wbase = warp * 32;

    float acc[2][8][4];
#pragma unroll
    for (int mt = 0; mt < 2; mt++)
#pragma unroll
        for (int nt = 0; nt < 8; nt++)
#pragma unroll
            for (int c = 0; c < 4; c++) acc[mt][nt][c] = 0.f;

    auto issue = [&](int t, int b) {
        uint32_t base = sb + (uint32_t)(b * G2BUF) * 4;
#pragma unroll
        for (int it = 0; it < 4; it++) {
            int idx = it * 128 + tid;
            int r = idx >> 2, c16 = idx & 3;
            cp16(base + (uint32_t)(r * GA_ST + c16 * 4) * 4,
                 &A[(size_t)(m0 + r) * DM + t * 32 + c16 * 8]);
        }
#pragma unroll
        for (int it = 0; it < 2; it++) {
            int idx = it * 128 + tid;
            int kp = idx >> 4, nc = idx & 15;
            cp16(base + (uint32_t)(128 * GA_ST + kp * GB_ST + nc * 4) * 4,
                 &Bp[(size_t)(t * 16 + kp) * DM + n0 + nc * 4]);
        }
        CP_COMMIT();
    };

    issue(0, 0);

    const int NT = DM / 32;
    for (int t = 0; t < NT; t++) {
        CP_WAIT_ALL();
        __syncthreads();
        if (t + 1 < NT) issue(t + 1, (t + 1) & 1);

        const uint32_t* Ab = sm + (t & 1) * G2BUF;
        const uint32_t* Bb = Ab + 128 * GA_ST;

#pragma unroll
        for (int c = 0; c < 2; c++) {
            int kcw = c * 8 + tg;
            uint32_t a[2][4];
#pragma unroll
            for (int mt = 0; mt < 2; mt++) {
                int r = wbase + mt * 16 + g;
                a[mt][0] = Ab[r * GA_ST + kcw];
                a[mt][1] = Ab[(r + 8) * GA_ST + kcw];
                a[mt][2] = Ab[r * GA_ST + kcw + 4];
                a[mt][3] = Ab[(r + 8) * GA_ST + kcw + 4];
            }
#pragma unroll
            for (int nt = 0; nt < 8; nt++) {
                int cn = nt * 8 + g;
                uint32_t b0 = Bb[kcw * GB_ST + cn];
                uint32_t b1 = Bb[(kcw + 4) * GB_ST + cn];
                mma_f16(acc[0][nt], a[0][0], a[0][1], a[0][2], a[0][3], b0, b1);
                mma_f16(acc[1][nt], a[1][0], a[1][1], a[1][2], a[1][3], b0, b1);
            }
        }
        __syncthreads();
    }

#pragma unroll
    for (int mt = 0; mt < 2; mt++)
#pragma unroll
        for (int nt = 0; nt < 8; nt++) {
            int r = m0 + wbase + mt * 16 + g;
            int c = n0 + nt * 8 + 2 * tg;
            float b0 = bias[c], b1 = bias[c + 1];
            *(float2*)&Cout[(size_t)r * DM + c] =
                make_float2(acc[mt][nt][0] + b0, acc[mt][nt][1] + b1);
            *(float2*)&Cout[(size_t)(r + 8) * DM + c] =
                make_float2(acc[mt][nt][2] + b0, acc[mt][nt][3] + b1);
        }
}

// ---------------------------------------------------------------------------
// Flash attention fp16 (round-15 exact: 64 q-rows, ldmatrix, 2-buffer,
// 3 blocks/SM, log2 softmax, ex2.f16x2, ones-mma sums). Best measured: 125us.
// ---------------------------------------------------------------------------
#define KT_ST 36
#define ABUF  (2 * 64 * KT_ST)

__global__ __launch_bounds__(128, 3) void attn16(float* dummy)
{
    __shared__ uint32_t sms[2 * ABUF];   // 36864 B
    const uint32_t sb = (uint32_t)__cvta_generic_to_shared(sms);

    const int h = blockIdx.y;
    const int t = blockIdx.x;
    const int iq = (t & 1) ? (63 - (t >> 1)) : (t >> 1);
    const int tid = threadIdx.x, warp = tid >> 5, lane = tid & 31;
    const int g = lane >> 2, tg = lane & 3;
    const int hoff = h * HD;
    const int qrow0 = iq * 64 + warp * 16 + g;

    const uint32_t lm_ofs =
        (uint32_t)(((lane >> 4) * 8 + (lane & 7)) * KT_ST + ((lane >> 3) & 1) * 4) * 4;

    const uint32_t* qw = (const uint32_t*)g_q16;
    uint32_t qf[4][4];
    {
        size_t b0 = ((size_t)qrow0 * DM + hoff) >> 1;
        size_t b1 = ((size_t)(qrow0 + 8) * DM + hoff) >> 1;
#pragma unroll
        for (int c = 0; c < 4; c++) {
            qf[c][0] = qw[b0 + c * 8 + tg];
            qf[c][1] = qw[b1 + c * 8 + tg];
            qf[c][2] = qw[b0 + c * 8 + tg + 4];
            qf[c][3] = qw[b1 + c * 8 + tg + 4];
        }
    }

    float of[8][4];
#pragma unroll
    for (int nt = 0; nt < 8; nt++)
#pragma unroll
        for (int c = 0; c < 4; c++) of[nt][c] = 0.f;
    float m0r = -1e30f, m1r = -1e30f, l0 = 0.f, l1 = 0.f;

    auto issue = [&](int kt, int b) {
        uint32_t base = sb + (uint32_t)(b * ABUF) * 4;
#pragma unroll
        for (int it = 0; it < 4; it++) {
            int idx = it * 128 + tid;
            int r = idx >> 3, c16 = idx & 7;
            cp16(base + (uint32_t)(r * KT_ST + c16 * 4) * 4,
                 &g_k16[(size_t)(kt * 64 + r) * DM + hoff + c16 * 8]);
            cp16(base + (uint32_t)(64 * KT_ST + r * KT_ST + c16 * 4) * 4,
                 &g_vT[(size_t)(hoff + r) * S_LEN + kt * 64 + c16 * 8]);
        }
        CP_COMMIT();
    };

    issue(0, 0);

    const int ktmax = iq;
    for (int kt = 0; kt <= ktmax; kt++) {
        CP_WAIT_ALL();
        __syncthreads();
        if (kt < ktmax) issue(kt + 1, (kt + 1) & 1);

        const uint32_t Kbase = sb + (uint32_t)((kt & 1) * ABUF) * 4 + lm_ofs;
        const uint32_t Vbase = Kbase + (uint32_t)(64 * KT_ST) * 4;

        float s[8][4];
#pragma unroll
        for (int nt = 0; nt < 8; nt++)
#pragma unroll
            for (int c = 0; c < 4; c++) s[nt][c] = 0.f;

#pragma unroll
        for (int c = 0; c < 4; c++) {
#pragma unroll
            for (int ntp = 0; ntp < 4; ntp++) {
                uint32_t b0a, b1a, b0b, b1b;
                ldsm4(b0a, b1a, b0b, b1b,
                      Kbase + (uint32_t)(ntp * 16 * KT_ST + c * 8) * 4);
                mma_f16(s[2 * ntp],     qf[c][0], qf[c][1], qf[c][2], qf[c][3], b0a, b1a);
                mma_f16(s[2 * ntp + 1], qf[c][0], qf[c][1], qf[c][2], qf[c][3], b0b, b1b);
            }
        }

        if (kt == iq) {
#pragma unroll
            for (int nt = 0; nt < 8; nt++) {
                int col = kt * 64 + nt * 8 + 2 * tg;
                if (col     > qrow0)     s[nt][0] = -1e30f;
                if (col + 1 > qrow0)     s[nt][1] = -1e30f;
                if (col     > qrow0 + 8) s[nt][2] = -1e30f;
                if (col + 1 > qrow0 + 8) s[nt][3] = -1e30f;
            }
        }

        float rm0 = -1e30f, rm1 = -1e30f;
#pragma unroll
        for (int nt = 0; nt < 8; nt++) {
            rm0 = fmaxf(rm0, fmaxf(s[nt][0], s[nt][1]));
            rm1 = fmaxf(rm1, fmaxf(s[nt][2], s[nt][3]));
        }
#pragma unroll
        for (int off = 1; off <= 2; off <<= 1) {
            rm0 = fmaxf(rm0, __shfl_xor_sync(0xFFFFFFFFu, rm0, off));
            rm1 = fmaxf(rm1, __shfl_xor_sync(0xFFFFFFFFu, rm1, off));
        }
        float nm0 = fmaxf(m0r, rm0), nm1 = fmaxf(m1r, rm1);
        float al0 = exp2f(m0r - nm0), al1 = exp2f(m1r - nm1);
        m0r = nm0;  m1r = nm1;
        l0 *= al0;  l1 *= al1;
#pragma unroll
        for (int nt = 0; nt < 8; nt++) {
            of[nt][0] *= al0; of[nt][1] *= al0;
            of[nt][2] *= al1; of[nt][3] *= al1;
        }

        uint32_t ah[4][4];
        uint32_t nm0p = f2h2(nm0, nm0), nm1p = f2h2(nm1, nm1);
#pragma unroll
        for (int c = 0; c < 4; c++) {
            ah[c][0] = ex2h2(hsub2u(f2h2(s[2*c][0],   s[2*c][1]),   nm0p));
            ah[c][1] = ex2h2(hsub2u(f2h2(s[2*c][2],   s[2*c][3]),   nm1p));
            ah[c][2] = ex2h2(hsub2u(f2h2(s[2*c+1][0], s[2*c+1][1]), nm0p));
            ah[c][3] = ex2h2(hsub2u(f2h2(s[2*c+1][2], s[2*c+1][3]), nm1p));
        }

        float sacc[4] = {0.f, 0.f, 0.f, 0.f};
#pragma unroll
        for (int c = 0; c < 4; c++) {
#pragma unroll
            for (int ntp = 0; ntp < 4; ntp++) {
                uint32_t b0a, b1a, b0b, b1b;
                ldsm4(b0a, b1a, b0b, b1b,
                      Vbase + (uint32_t)(ntp * 16 * KT_ST + c * 8) * 4);
                mma_f16(of[2 * ntp],     ah[c][0], ah[c][1], ah[c][2], ah[c][3], b0a, b1a);
                mma_f16(of[2 * ntp + 1], ah[c][0], ah[c][1], ah[c][2], ah[c][3], b0b, b1b);
            }
            mma_f16(sacc, ah[c][0], ah[c][1], ah[c][2], ah[c][3], ONESH2, ONESH2);
        }
        l0 += sacc[0];
        l1 += sacc[2];
    }

    uint32_t* out = (uint32_t*)g_a16;
    float inv0 = 1.f / l0, inv1 = 1.f / l1;
#pragma unroll
    for (int nt = 0; nt < 8; nt++) {
        int c = hoff + nt * 8 + 2 * tg;
        out[((size_t)qrow0 * DM + c) >> 1] =
            f2h2(of[nt][0] * inv0, of[nt][1] * inv0);
        out[((size_t)(qrow0 + 8) * DM + c) >> 1] =
            f2h2(of[nt][2] * inv1, of[nt][3] * inv1);
    }
}

// ---------------------------------------------------------------------------
// Launch
// ---------------------------------------------------------------------------
extern "C" void kernel_launch(void* const* d_in, const int* in_sizes, int n_in,
                              void* d_out, int out_size)
{
    const float* Q  = (const float*)d_in[0];
    const float* K  = (const float*)d_in[1];
    const float* V  = (const float*)d_in[2];
    const float* Wq = (const float*)d_in[3];
    const float* Wk = (const float*)d_in[4];
    const float* Wv = (const float*)d_in[5];
    const float* Wo = (const float*)d_in[6];
    const float* bo = (const float*)d_in[7];
    float* out = (float*)d_out;

    static bool attr_set = false;
    if (!attr_set) {
        cudaFuncSetAttribute(proj3, cudaFuncAttributeMaxDynamicSharedMemorySize,
                             GEMM_SMEM);
        cudaFuncSetAttribute(outg, cudaFuncAttributeMaxDynamicSharedMemorySize,
                             GEMM2_SMEM);
        attr_set = true;
    }

    prep<<<dim3(S_LEN * DM / 8 / 256, 7), 256>>>(Q, K, V, Wq, Wk, Wv, Wo);

    proj3<<<dim3(DM / 64, S_LEN / 256, 3), 128, GEMM_SMEM>>>(nullptr);

    attn16<<<dim3(S_LEN / 64, NH), 128>>>(nullptr);

    outg<<<dim3(DM / 64, S_LEN / 128), 128, GEMM2_SMEM>>>(bo, out);
}